// round 2
// baseline (speedup 1.0000x reference)
#include <cuda_runtime.h>
#include <cuda_bf16.h>
#include <math.h>

// ---------------------------------------------------------------------------
// Problem constants
// ---------------------------------------------------------------------------
#define B_    256
#define K_    4
#define CIN_  256
#define CV_   128
#define COUT_ 256
#define HW_   256      // 16*16
#define LOG2PI 1.8378770664093453f

// Output layout (concatenated flat float32):
// out(16777216), z(8388608), logprob_p(33554432), logprob_q(8388608),
// kl_total(1), q_mu(8388608), q_lv(8388608), y(1024), cross_entropy(1)
#define OFF_OUT 0
#define OFF_Z   16777216
#define OFF_LPP 25165824
#define OFF_LPQ 58720256
#define OFF_KLT 67108864
#define OFF_QMU 67108865
#define OFF_QLV 75497473
#define OFF_Y   83886081
#define OFF_CE  83887105

// ---------------------------------------------------------------------------
// Scratch (device-global; no runtime allocation)
// ---------------------------------------------------------------------------
__device__ float  g_h[B_ * CV_ * HW_];        // qy conv output (relu)     33.5MB
__device__ float  g_qmod[B_ * CIN_ * HW_];    // gamma*q+beta              67MB
__device__ float  g_t1[B_ * 2 * CV_ * HW_];   // relu(conv(qmod,qz1))      67MB
__device__ float  g_qz[B_ * 2 * CV_ * HW_];   // conv(t1,qz2)              67MB
__device__ float  g_logits[B_ * K_];
__device__ float  g_gamma[B_ * CIN_];
__device__ float  g_beta[B_ * CIN_];
__device__ double g_kl_sum;
__device__ double g_js_mean;

// ---------------------------------------------------------------------------
// Helpers
// ---------------------------------------------------------------------------
__device__ __forceinline__ float clamp10(float v) {
    return fminf(fmaxf(v, -10.0f), 10.0f);
}
__device__ __forceinline__ float std_from_lv(float lv) {
    return (lv < 0.0f) ? expf(0.5f * lv) : (1.0f + lv);
}
__device__ __forceinline__ float logstd_from_lv(float lv) {
    return (lv < 0.0f) ? 0.5f * lv : log1pf(lv);
}

// ---------------------------------------------------------------------------
// 3x3 same conv, NCHW, 16x16 spatial.
// Block: 256 threads = 16x16 pixels. Each block: 2 images x 16 out channels.
// grid.x = COUT/16, grid.y = B/2
// ---------------------------------------------------------------------------
template <int CIN, int COUT, bool RELU>
__global__ __launch_bounds__(256)
void conv3x3_kernel(const float* __restrict__ in, const float* __restrict__ w,
                    const float* __restrict__ bias, float* __restrict__ out) {
    constexpr int CT = 8;   // cin tile
    constexpr int OT = 16;  // cout tile
    __shared__ float s_in[2 * CT * 324];  // 2 imgs * 8 ch * 18*18
    __shared__ float s_w[OT * CT * 9];    // [co][ci][t]

    const int tid = threadIdx.x;
    const int ty = tid >> 4;
    const int tx = tid & 15;
    const int cout0 = blockIdx.x * OT;
    const int b0 = blockIdx.y * 2;

    float acc0[OT], acc1[OT];
#pragma unroll
    for (int i = 0; i < OT; i++) { acc0[i] = 0.0f; acc1[i] = 0.0f; }

    for (int cb = 0; cb < CIN; cb += CT) {
        __syncthreads();
        // load input halo tiles: 2*8*324 = 5184 floats
        for (int i = tid; i < 2 * CT * 324; i += 256) {
            int img = i / (CT * 324);
            int rem = i - img * (CT * 324);
            int ci = rem / 324;
            int p = rem - ci * 324;
            int yy = p / 18;
            int xx = p - yy * 18;
            int gy = yy - 1, gx = xx - 1;
            float v = 0.0f;
            if (gy >= 0 && gy < 16 && gx >= 0 && gx < 16)
                v = in[(((b0 + img) * CIN + cb + ci) * 16 + gy) * 16 + gx];
            s_in[i] = v;
        }
        // load weights: 16*8*9 = 1152 floats
        for (int i = tid; i < OT * CT * 9; i += 256) {
            int co = i / (CT * 9);
            int rem = i - co * (CT * 9);
            s_w[i] = w[(cout0 + co) * CIN * 9 + cb * 9 + rem];
        }
        __syncthreads();

        for (int ci = 0; ci < CT; ci++) {
            float a0[9], a1[9];
            const float* p0 = &s_in[ci * 324 + ty * 18 + tx];
            const float* p1 = &s_in[(CT + ci) * 324 + ty * 18 + tx];
#pragma unroll
            for (int dy = 0; dy < 3; dy++)
#pragma unroll
                for (int dx = 0; dx < 3; dx++) {
                    a0[dy * 3 + dx] = p0[dy * 18 + dx];
                    a1[dy * 3 + dx] = p1[dy * 18 + dx];
                }
            const float* wp = &s_w[ci * 9];
#pragma unroll
            for (int co = 0; co < OT; co++) {
#pragma unroll
                for (int t = 0; t < 9; t++) {
                    float wv = wp[co * CT * 9 + t];
                    acc0[co] += wv * a0[t];
                    acc1[co] += wv * a1[t];
                }
            }
        }
    }

#pragma unroll
    for (int co = 0; co < OT; co++) {
        float bz = bias[cout0 + co];
        float v0 = acc0[co] + bz;
        float v1 = acc1[co] + bz;
        if (RELU) { v0 = fmaxf(v0, 0.0f); v1 = fmaxf(v1, 0.0f); }
        out[((b0 + 0) * COUT + cout0 + co) * HW_ + tid] = v0;
        out[((b0 + 1) * COUT + cout0 + co) * HW_ + tid] = v1;
    }
}

// ---------------------------------------------------------------------------
// qy_lin: logits[b,k] = sum_i h[b,i]*w[k,i] + bias[k]. One block per b.
// ---------------------------------------------------------------------------
__global__ __launch_bounds__(256)
void qy_lin_kernel(const float* __restrict__ h, const float* __restrict__ w,
                   const float* __restrict__ bias, float* __restrict__ logits) {
    const int b = blockIdx.x;
    const int tid = threadIdx.x;
    const int N = CV_ * HW_;  // 32768
    float acc[K_] = {0, 0, 0, 0};
    const float* hb = h + b * N;
    for (int i = tid; i < N; i += 256) {
        float hv = hb[i];
#pragma unroll
        for (int k = 0; k < K_; k++) acc[k] += hv * w[k * N + i];
    }
    __shared__ float red[256];
#pragma unroll
    for (int k = 0; k < K_; k++) {
        red[tid] = acc[k];
        __syncthreads();
        for (int s = 128; s > 0; s >>= 1) {
            if (tid < s) red[tid] += red[tid + s];
            __syncthreads();
        }
        if (tid == 0) logits[b * K_ + k] = red[0] + bias[k];
        __syncthreads();
    }
}

// ---------------------------------------------------------------------------
// Per-batch small work: gumbel softmax y, cross_entropy, js, gamma/beta.
// Single block of 256 threads (one thread per batch element).
// ---------------------------------------------------------------------------
__global__ __launch_bounds__(256)
void small_kernel(const float* __restrict__ logits, const float* __restrict__ u,
                  const int* __restrict__ label,
                  const float* __restrict__ gamma_w, const float* __restrict__ gamma_b,
                  const float* __restrict__ beta_w, const float* __restrict__ beta_b,
                  float* __restrict__ gamma, float* __restrict__ beta,
                  float* __restrict__ out) {
    const int b = threadIdx.x;
    float l[K_], y[K_];
#pragma unroll
    for (int k = 0; k < K_; k++) l[k] = logits[b * K_ + k];

    // gumbel softmax (TAU=1)
    float s[K_];
    float mx = -1e30f;
#pragma unroll
    for (int k = 0; k < K_; k++) {
        float uu = u[b * K_ + k];
        float g = -logf(-logf(uu));
        s[k] = l[k] + g;
        mx = fmaxf(mx, s[k]);
    }
    float sum = 0.0f;
#pragma unroll
    for (int k = 0; k < K_; k++) { y[k] = expf(s[k] - mx); sum += y[k]; }
    float inv = 1.0f / sum;
#pragma unroll
    for (int k = 0; k < K_; k++) {
        y[k] *= inv;
        out[OFF_Y + b * K_ + k] = y[k];
    }

    // cross entropy: lse(l) - l[label]
    float mx2 = fmaxf(fmaxf(l[0], l[1]), fmaxf(l[2], l[3]));
    float se = 0.0f;
#pragma unroll
    for (int k = 0; k < K_; k++) se += expf(l[k] - mx2);
    float lse = logf(se) + mx2;
    int lbl = label[b];
    float ce_b = lse - l[lbl];

    // JS to uniform prior 1/K
    const float prior = 1.0f / K_;
    float t1 = 0.0f, t2 = 0.0f;
#pragma unroll
    for (int k = 0; k < K_; k++) {
        float m = 0.5f * (y[k] + prior);
        t1 += y[k] * logf(y[k] / (m + 1e-10f));
        t2 += prior * logf(prior / (m + 1e-10f));
    }
    float js_b = 0.5f * t1 + 0.5f * t2;

    // gamma / beta (B x 256)
    for (int c = 0; c < CIN_; c++) {
        float gw = gamma_w[c * K_ + 0] * l[0] + gamma_w[c * K_ + 1] * l[1] +
                   gamma_w[c * K_ + 2] * l[2] + gamma_w[c * K_ + 3] * l[3];
        float bw = beta_w[c * K_ + 0] * l[0] + beta_w[c * K_ + 1] * l[1] +
                   beta_w[c * K_ + 2] * l[2] + beta_w[c * K_ + 3] * l[3];
        gamma[b * CIN_ + c] = gw + gamma_b[c];
        beta[b * CIN_ + c] = bw + beta_b[c];
    }

    // reduce ce and js over 256 threads
    __shared__ double r1[256], r2[256];
    r1[b] = (double)ce_b;
    r2[b] = (double)js_b;
    __syncthreads();
    for (int st = 128; st > 0; st >>= 1) {
        if (b < st) { r1[b] += r1[b + st]; r2[b] += r2[b + st]; }
        __syncthreads();
    }
    if (b == 0) {
        out[OFF_CE] = (float)(r1[0] / (double)B_);
        g_js_mean = r2[0] / (double)B_;
        g_kl_sum = 0.0;
    }
}

// ---------------------------------------------------------------------------
// q_mod = gamma[b,c]*q + beta[b,c]
// ---------------------------------------------------------------------------
__global__ __launch_bounds__(256)
void qmod_kernel(const float* __restrict__ q, const float* __restrict__ gamma,
                 const float* __restrict__ beta, float* __restrict__ qmod) {
    int idx = blockIdx.x * 256 + threadIdx.x;  // B*CIN*HW threads
    int bc = idx >> 8;  // b*CIN + c
    qmod[idx] = gamma[bc] * q[idx] + beta[bc];
}

// ---------------------------------------------------------------------------
// z / q_mu / q_lv / logprob_q. (z - q_mu)/q_std == eps exactly.
// ---------------------------------------------------------------------------
__global__ __launch_bounds__(256)
void z_kernel(const float* __restrict__ qz, const float* __restrict__ eps,
              float* __restrict__ out) {
    int idx = blockIdx.x * 256 + threadIdx.x;  // B*CV*HW
    int b = idx >> 15;            // / 32768
    int r = idx & 32767;
    int c = r >> 8;
    int pix = r & 255;
    float mu = clamp10(qz[((b * (2 * CV_) + c) << 8) + pix]);
    float lv = clamp10(qz[((b * (2 * CV_) + CV_ + c) << 8) + pix]);
    float sd = std_from_lv(lv);
    float lsd = logstd_from_lv(lv);
    float e = eps[idx];
    float z = mu + sd * e;
    out[OFF_Z + idx] = z;
    out[OFF_QMU + idx] = mu;
    out[OFF_QLV + idx] = lv;
    out[OFF_LPQ + idx] = -0.5f * e * e - lsd - 0.5f * LOG2PI;
}

// ---------------------------------------------------------------------------
// logprob_p (all K, transposed layout [b,c,pix,k]) + fused KL(label) reduce
// ---------------------------------------------------------------------------
__global__ __launch_bounds__(256)
void pk_kernel(const float* __restrict__ p, const int* __restrict__ label,
               float* __restrict__ out) {
    int idx = blockIdx.x * 256 + threadIdx.x;  // B*CV*HW threads
    int b = idx >> 15;
    int r = idx & 32767;
    int c = r >> 8;
    int pix = r & 255;
    int lbl = label[b];

    float z = out[OFF_Z + idx];
    float qm = out[OFF_QMU + idx];
    float qlv = out[OFF_QLV + idx];
    float qs = std_from_lv(qlv);
    float lqs = logstd_from_lv(qlv);

    float4 lp;
    float klv = 0.0f;
#pragma unroll
    for (int k = 0; k < K_; k++) {
        int base = ((b * (2 * K_ * CV_) + k * CV_ + c) << 8) + pix;
        float pm = clamp10(p[base]);
        float plv = clamp10(p[base + (K_ * CV_ << 8)]);  // +512 channels
        float ps = std_from_lv(plv);
        float lps = logstd_from_lv(plv);
        float inv_ps = 1.0f / ps;
        float d = (z - pm) * inv_ps;
        float v = -0.5f * d * d - lps - 0.5f * LOG2PI;
        if (k == 0) lp.x = v;
        else if (k == 1) lp.y = v;
        else if (k == 2) lp.z = v;
        else lp.w = v;
        if (k == lbl) {
            float dd = qm - pm;
            klv = lps - lqs + (qs * qs + dd * dd) * (0.5f * inv_ps * inv_ps) - 0.5f;
        }
    }
    reinterpret_cast<float4*>(out + OFF_LPP)[idx] = lp;

    __shared__ float red[256];
    red[threadIdx.x] = klv;
    __syncthreads();
    for (int s = 128; s > 0; s >>= 1) {
        if (threadIdx.x < s) red[threadIdx.x] += red[threadIdx.x + s];
        __syncthreads();
    }
    if (threadIdx.x == 0) atomicAdd(&g_kl_sum, (double)red[0]);
}

__global__ void finalize_kernel(float* __restrict__ out) {
    out[OFF_KLT] = (float)(g_kl_sum / (double)(B_ * CV_ * HW_) + g_js_mean);
}

// ---------------------------------------------------------------------------
// Launch
// ---------------------------------------------------------------------------
extern "C" void kernel_launch(void* const* d_in, const int* in_sizes, int n_in,
                              void* d_out, int out_size) {
    const float* p_params = (const float*)d_in[0];
    const float* q_params = (const float*)d_in[1];
    const int*   label    = (const int*)d_in[2];
    const float* eps      = (const float*)d_in[3];
    const float* u_gumbel = (const float*)d_in[4];
    const float* qy_conv_w = (const float*)d_in[5];
    const float* qy_conv_b = (const float*)d_in[6];
    const float* qy_lin_w  = (const float*)d_in[7];
    const float* qy_lin_b  = (const float*)d_in[8];
    const float* gamma_w   = (const float*)d_in[9];
    const float* gamma_b   = (const float*)d_in[10];
    const float* beta_w    = (const float*)d_in[11];
    const float* beta_b    = (const float*)d_in[12];
    const float* qz1_w     = (const float*)d_in[13];
    const float* qz1_b     = (const float*)d_in[14];
    const float* qz2_w     = (const float*)d_in[15];
    const float* qz2_b     = (const float*)d_in[16];
    const float* out_w     = (const float*)d_in[17];
    const float* out_b     = (const float*)d_in[18];
    float* out = (float*)d_out;

    float *h, *qmod, *t1, *qz, *logits, *gamma, *beta;
    cudaGetSymbolAddress((void**)&h, g_h);
    cudaGetSymbolAddress((void**)&qmod, g_qmod);
    cudaGetSymbolAddress((void**)&t1, g_t1);
    cudaGetSymbolAddress((void**)&qz, g_qz);
    cudaGetSymbolAddress((void**)&logits, g_logits);
    cudaGetSymbolAddress((void**)&gamma, g_gamma);
    cudaGetSymbolAddress((void**)&beta, g_beta);

    // 1) h = relu(conv(q_params, qy_conv))
    conv3x3_kernel<CIN_, CV_, true><<<dim3(CV_ / 16, B_ / 2), 256>>>(
        q_params, qy_conv_w, qy_conv_b, h);
    // 2) qy_logits
    qy_lin_kernel<<<B_, 256>>>(h, qy_lin_w, qy_lin_b, logits);
    // 3) y / ce / js / gamma / beta
    small_kernel<<<1, 256>>>(logits, u_gumbel, label, gamma_w, gamma_b,
                             beta_w, beta_b, gamma, beta, out);
    // 4) q_mod
    qmod_kernel<<<(B_ * CIN_ * HW_) / 256, 256>>>(q_params, gamma, beta, qmod);
    // 5) t1 = relu(conv(q_mod, qz1))
    conv3x3_kernel<CIN_, 2 * CV_, true><<<dim3((2 * CV_) / 16, B_ / 2), 256>>>(
        qmod, qz1_w, qz1_b, t1);
    // 6) qz_params = conv(t1, qz2)
    conv3x3_kernel<2 * CV_, 2 * CV_, false><<<dim3((2 * CV_) / 16, B_ / 2), 256>>>(
        t1, qz2_w, qz2_b, qz);
    // 7) z / q_mu / q_lv / logprob_q
    z_kernel<<<(B_ * CV_ * HW_) / 256, 256>>>(qz, eps, out);
    // 8) out = conv(z, out_w)
    conv3x3_kernel<CV_, COUT_, false><<<dim3(COUT_ / 16, B_ / 2), 256>>>(
        out + OFF_Z, out_w, out_b, out + OFF_OUT);
    // 9) logprob_p + kl
    pk_kernel<<<(B_ * CV_ * HW_) / 256, 256>>>(p_params, label, out);
    // 10) kl_total
    finalize_kernel<<<1, 1>>>(out);
}

// round 5
// speedup vs baseline: 5.0551x; 5.0551x over previous
#include <cuda_runtime.h>
#include <cuda_bf16.h>
#include <math.h>
#include <stdint.h>

// ---------------------------------------------------------------------------
// Problem constants
// ---------------------------------------------------------------------------
#define B_    256
#define K_    4
#define CIN_  256
#define CV_   128
#define COUT_ 256
#define HW_   256      // 16*16
#define LOG2PI 1.8378770664093453f

// Output layout (concatenated flat float32)
#define OFF_OUT 0
#define OFF_Z   16777216
#define OFF_LPP 25165824
#define OFF_LPQ 58720256
#define OFF_KLT 67108864
#define OFF_QMU 67108865   // ODD -> never access as float4!
#define OFF_QLV 75497473   // ODD -> never access as float4!
#define OFF_Y   83886081
#define OFF_CE  83887105

// ---------------------------------------------------------------------------
// Scratch (device-global; no runtime allocation). 16B-aligned for vector ops.
// ---------------------------------------------------------------------------
__device__ __align__(16) float  g_h[B_ * CV_ * HW_];
__device__ __align__(16) float  g_qmod[B_ * CIN_ * HW_];
__device__ __align__(16) float  g_t1[B_ * 2 * CV_ * HW_];
__device__ __align__(16) float  g_qz[B_ * 2 * CV_ * HW_];
__device__ __align__(16) float  g_logits[B_ * K_];
__device__ __align__(16) float  g_gamma[B_ * CIN_];
__device__ __align__(16) float  g_beta[B_ * CIN_];
__device__ double g_kl_sum;
__device__ double g_js_mean;

// Fragment-ordered bf16-split weights for the 4 convs.
#define WOFF_QY  0
#define WOFF_QZ1 294912
#define WOFF_QZ2 884736
#define WOFF_OUT 1474560
#define WBUF_TOTAL 1769472
__device__ __align__(16) uint32_t g_wbuf[WBUF_TOTAL];

// ---------------------------------------------------------------------------
// Helpers
// ---------------------------------------------------------------------------
__device__ __forceinline__ float clamp10(float v) {
    return fminf(fmaxf(v, -10.0f), 10.0f);
}
__device__ __forceinline__ float std_from_lv(float lv) {
    return (lv < 0.0f) ? expf(0.5f * lv) : (1.0f + lv);
}
__device__ __forceinline__ float logstd_from_lv(float lv) {
    return (lv < 0.0f) ? 0.5f * lv : log1pf(lv);
}
__device__ __forceinline__ uint32_t smem_u32(const void* p) {
    return (uint32_t)__cvta_generic_to_shared(p);
}
__device__ __forceinline__ uint32_t pack_bf16(__nv_bfloat16 a, __nv_bfloat16 b) {
    return (uint32_t)__bfloat16_as_ushort(a) | ((uint32_t)__bfloat16_as_ushort(b) << 16);
}
__device__ __forceinline__ void ldsm4(uint32_t r[4], uint32_t addr) {
    asm volatile("ldmatrix.sync.aligned.m8n8.x4.shared.b16 {%0,%1,%2,%3}, [%4];"
                 : "=r"(r[0]), "=r"(r[1]), "=r"(r[2]), "=r"(r[3]) : "r"(addr));
}
__device__ __forceinline__ void mma16816(float c[4], const uint32_t a[4], const uint32_t b[2]) {
    asm volatile(
        "mma.sync.aligned.m16n8k16.row.col.f32.bf16.bf16.f32 "
        "{%0,%1,%2,%3}, {%4,%5,%6,%7}, {%8,%9}, {%0,%1,%2,%3};"
        : "+f"(c[0]), "+f"(c[1]), "+f"(c[2]), "+f"(c[3])
        : "r"(a[0]), "r"(a[1]), "r"(a[2]), "r"(a[3]), "r"(b[0]), "r"(b[1]));
}

// ---------------------------------------------------------------------------
// Weight prep: fp32 w[co][ci][9] -> fragment-ordered bf16-split words.
// slot s in [0,4608): s = ((t*8+nt)*32 + lane)*2 + reg
// word[hl=0] at blk*9216 + (t*8+nt)*128 + lane*2 + reg ; hl=1 at +64
// ---------------------------------------------------------------------------
__global__ void wprep_kernel(const float* __restrict__ w, uint32_t* __restrict__ dst,
                             int CIN, int CTILES, int total) {
    int idx = blockIdx.x * 256 + threadIdx.x;
    if (idx >= total) return;
    int s = idx % 4608;
    int blk = idx / 4608;             // chunk*CTILES + ctile
    int chunk = blk / CTILES;
    int ctile = blk % CTILES;
    int reg = s & 1;
    int lane = (s >> 1) & 31;
    int nt = (s >> 6) & 7;
    int t = s >> 9;
    int i = lane & 3, g = lane >> 2;
    int ci = chunk * 16 + 2 * i + 8 * reg;
    int co = ctile * 64 + nt * 8 + g;
    float f0 = w[(co * CIN + ci) * 9 + t];
    float f1 = w[(co * CIN + ci + 1) * 9 + t];
    __nv_bfloat16 h0 = __float2bfloat16(f0), h1 = __float2bfloat16(f1);
    __nv_bfloat16 l0 = __float2bfloat16(f0 - __bfloat162float(h0));
    __nv_bfloat16 l1 = __float2bfloat16(f1 - __bfloat162float(h1));
    uint32_t base = (uint32_t)blk * 9216u + (uint32_t)(t * 8 + nt) * 128u + lane * 2 + reg;
    dst[base] = pack_bf16(h0, h1);
    dst[base + 64] = pack_bf16(l0, l1);
}

// ---------------------------------------------------------------------------
// Implicit-GEMM 3x3 conv via mma.sync bf16-split.
// Block: 256 threads (8 warps). Tile: 1 image x 64 couts x 256 pixels.
// grid = (COUT/64, B). Dynamic smem: s_a (257*80 B) + s_b (9216 words).
// ---------------------------------------------------------------------------
#define CONV_SMEM (257 * 80 + 9216 * 4)   // 57424

template <int CIN, int COUT, bool RELU>
__global__ __launch_bounds__(256, 2)
void conv_mma_kernel(const float* __restrict__ in, const uint32_t* __restrict__ wbuf,
                     const float* __restrict__ bias, float* __restrict__ out) {
    extern __shared__ char smem[];
    char* s_a = smem;                                   // 257 rows * 80 B
    uint32_t* s_b = (uint32_t*)(smem + 257 * 80);       // 9216 words
    constexpr int CHUNKS = CIN / 16;
    constexpr int CTILES = COUT / 64;

    const int tid = threadIdx.x;
    const int lane = tid & 31;
    const int warp = tid >> 5;
    const int ctile = blockIdx.x;
    const int b = blockIdx.y;
    const int cout0 = ctile * 64;

    const uint32_t sa_base = smem_u32(s_a);

    // zero OOB row (row 256): 20 words
    if (tid < 20) ((uint32_t*)(s_a + 256 * 80))[tid] = 0;

    float acc[2][8][4];
#pragma unroll
    for (int mt = 0; mt < 2; mt++)
#pragma unroll
        for (int nt = 0; nt < 8; nt++)
#pragma unroll
            for (int j = 0; j < 4; j++) acc[mt][nt][j] = 0.0f;

    const int rowsel = lane & 15;   // x coordinate within the 16-pixel row
    const int khalf = lane >> 4;    // k half select (bytes +0 / +16)

    for (int ch = 0; ch < CHUNKS; ch++) {
        __syncthreads();
        // ---- load A tile: 16 channels x 256 pixels, bf16 hi/lo split ----
        const float* inp = in + (((size_t)b * CIN + ch * 16) << 8);
#pragma unroll
        for (int ci = 0; ci < 16; ci += 2) {
            float v0 = inp[(ci << 8) + tid];
            float v1 = inp[((ci + 1) << 8) + tid];
            __nv_bfloat16 h0 = __float2bfloat16(v0);
            __nv_bfloat16 h1 = __float2bfloat16(v1);
            __nv_bfloat16 l0 = __float2bfloat16(v0 - __bfloat162float(h0));
            __nv_bfloat16 l1 = __float2bfloat16(v1 - __bfloat162float(h1));
            *(uint32_t*)(s_a + tid * 80 + ci * 2) = pack_bf16(h0, h1);
            *(uint32_t*)(s_a + tid * 80 + 32 + ci * 2) = pack_bf16(l0, l1);
        }
        // ---- load B tile: 2304 uint4 (fragment-linear) ----
        const uint4* src = (const uint4*)(wbuf + ((size_t)(ch * CTILES + ctile)) * 9216u);
        uint4* dstb = (uint4*)s_b;
#pragma unroll
        for (int k = 0; k < 9; k++) dstb[tid + k * 256] = src[tid + k * 256];
        __syncthreads();

        // ---- compute ----
#pragma unroll
        for (int dy = 0; dy < 3; dy++) {
#pragma unroll
            for (int dx = 0; dx < 3; dx++) {
                const int t = dy * 3 + dx;
                const int sx = rowsel + dx - 1;
                const bool colok = (unsigned)sx < 16u;
#pragma unroll
                for (int mt = 0; mt < 2; mt++) {
                    const int y = warp * 2 + mt;
                    const int sy = y + dy - 1;
                    const bool ok = colok && ((unsigned)sy < 16u);
                    const int spix = ok ? (sy * 16 + sx) : 256;
                    const uint32_t addr = sa_base + (uint32_t)spix * 80u + (uint32_t)khalf * 16u;
                    uint32_t ah[4], al[4];
                    ldsm4(ah, addr);
                    ldsm4(al, addr + 32u);
#pragma unroll
                    for (int nt = 0; nt < 8; nt++) {
                        const int boff = (t * 8 + nt) * 128 + lane * 2;
                        uint2 bh = *(const uint2*)(s_b + boff);
                        uint2 bl = *(const uint2*)(s_b + boff + 64);
                        uint32_t bhw[2] = {bh.x, bh.y};
                        uint32_t blw[2] = {bl.x, bl.y};
                        mma16816(acc[mt][nt], ah, bhw);
                        mma16816(acc[mt][nt], ah, blw);
                        mma16816(acc[mt][nt], al, bhw);
                    }
                }
            }
        }
    }

    // ---- epilogue: D[m=pixel][n=cout] -> out[b][co][pix], bias (+relu) ----
    const int g = lane >> 2;
    const int i2 = (lane & 3) * 2;
#pragma unroll
    for (int nt = 0; nt < 8; nt++) {
        const int co = cout0 + nt * 8 + i2;
        const float bz0 = bias[co];
        const float bz1 = bias[co + 1];
        float* o = out + (((size_t)b * COUT + co) << 8);
#pragma unroll
        for (int mt = 0; mt < 2; mt++) {
            const int pixa = warp * 32 + mt * 16 + g;
            float v0 = acc[mt][nt][0] + bz0;
            float v1 = acc[mt][nt][1] + bz1;
            float v2 = acc[mt][nt][2] + bz0;
            float v3 = acc[mt][nt][3] + bz1;
            if (RELU) {
                v0 = fmaxf(v0, 0.0f); v1 = fmaxf(v1, 0.0f);
                v2 = fmaxf(v2, 0.0f); v3 = fmaxf(v3, 0.0f);
            }
            o[pixa] = v0;
            o[256 + pixa] = v1;
            o[pixa + 8] = v2;
            o[256 + pixa + 8] = v3;
        }
    }
}

// ---------------------------------------------------------------------------
// qy_lin: logits[b,k] = sum_i h[b,i]*w[k,i] + bias[k]. One block per b.
// ---------------------------------------------------------------------------
__global__ __launch_bounds__(256)
void qy_lin_kernel(const float* __restrict__ h, const float* __restrict__ w,
                   const float* __restrict__ bias, float* __restrict__ logits) {
    const int b = blockIdx.x;
    const int tid = threadIdx.x;
    const int N = CV_ * HW_;     // 32768
    const int N4 = N / 4;
    float acc[K_] = {0, 0, 0, 0};
    const float4* hb = (const float4*)(h + (size_t)b * N);
    for (int i = tid; i < N4; i += 256) {
        float4 hv = hb[i];
#pragma unroll
        for (int k = 0; k < K_; k++) {
            float4 wv = ((const float4*)(w + (size_t)k * N))[i];
            acc[k] += hv.x * wv.x + hv.y * wv.y + hv.z * wv.z + hv.w * wv.w;
        }
    }
    __shared__ float red[256];
#pragma unroll
    for (int k = 0; k < K_; k++) {
        red[tid] = acc[k];
        __syncthreads();
        for (int s = 128; s > 0; s >>= 1) {
            if (tid < s) red[tid] += red[tid + s];
            __syncthreads();
        }
        if (tid == 0) logits[b * K_ + k] = red[0] + bias[k];
        __syncthreads();
    }
}

// ---------------------------------------------------------------------------
// Per-batch small work: gumbel softmax y, cross_entropy, js, gamma/beta.
// ---------------------------------------------------------------------------
__global__ __launch_bounds__(256)
void small_kernel(const float* __restrict__ logits, const float* __restrict__ u,
                  const int* __restrict__ label,
                  const float* __restrict__ gamma_w, const float* __restrict__ gamma_b,
                  const float* __restrict__ beta_w, const float* __restrict__ beta_b,
                  float* __restrict__ gamma, float* __restrict__ beta,
                  float* __restrict__ out) {
    const int b = threadIdx.x;
    float l[K_], y[K_];
#pragma unroll
    for (int k = 0; k < K_; k++) l[k] = logits[b * K_ + k];

    float s[K_];
    float mx = -1e30f;
#pragma unroll
    for (int k = 0; k < K_; k++) {
        float uu = u[b * K_ + k];
        float g = -logf(-logf(uu));
        s[k] = l[k] + g;
        mx = fmaxf(mx, s[k]);
    }
    float sum = 0.0f;
#pragma unroll
    for (int k = 0; k < K_; k++) { y[k] = expf(s[k] - mx); sum += y[k]; }
    float inv = 1.0f / sum;
#pragma unroll
    for (int k = 0; k < K_; k++) {
        y[k] *= inv;
        out[OFF_Y + b * K_ + k] = y[k];
    }

    float mx2 = fmaxf(fmaxf(l[0], l[1]), fmaxf(l[2], l[3]));
    float se = 0.0f;
#pragma unroll
    for (int k = 0; k < K_; k++) se += expf(l[k] - mx2);
    float lse = logf(se) + mx2;
    int lbl = label[b];
    float ce_b = lse - l[lbl];

    const float prior = 1.0f / K_;
    float t1 = 0.0f, t2 = 0.0f;
#pragma unroll
    for (int k = 0; k < K_; k++) {
        float m = 0.5f * (y[k] + prior);
        t1 += y[k] * logf(y[k] / (m + 1e-10f));
        t2 += prior * logf(prior / (m + 1e-10f));
    }
    float js_b = 0.5f * t1 + 0.5f * t2;

    for (int c = 0; c < CIN_; c++) {
        float gw = gamma_w[c * K_ + 0] * l[0] + gamma_w[c * K_ + 1] * l[1] +
                   gamma_w[c * K_ + 2] * l[2] + gamma_w[c * K_ + 3] * l[3];
        float bw = beta_w[c * K_ + 0] * l[0] + beta_w[c * K_ + 1] * l[1] +
                   beta_w[c * K_ + 2] * l[2] + beta_w[c * K_ + 3] * l[3];
        gamma[b * CIN_ + c] = gw + gamma_b[c];
        beta[b * CIN_ + c] = bw + beta_b[c];
    }

    __shared__ double r1[256], r2[256];
    r1[b] = (double)ce_b;
    r2[b] = (double)js_b;
    __syncthreads();
    for (int st = 128; st > 0; st >>= 1) {
        if (b < st) { r1[b] += r1[b + st]; r2[b] += r2[b + st]; }
        __syncthreads();
    }
    if (b == 0) {
        out[OFF_CE] = (float)(r1[0] / (double)B_);
        g_js_mean = r2[0] / (double)B_;
        g_kl_sum = 0.0;
    }
}

// ---------------------------------------------------------------------------
// q_mod = gamma[b,c]*q + beta[b,c]  (float4)
// ---------------------------------------------------------------------------
__global__ __launch_bounds__(256)
void qmod_kernel(const float* __restrict__ q, const float* __restrict__ gamma,
                 const float* __restrict__ beta, float* __restrict__ qmod) {
    int idx = blockIdx.x * 256 + threadIdx.x;   // B*CIN*HW/4 threads
    int bc = idx >> 6;
    float ga = gamma[bc], be = beta[bc];
    float4 v = ((const float4*)q)[idx];
    v.x = ga * v.x + be; v.y = ga * v.y + be;
    v.z = ga * v.z + be; v.w = ga * v.w + be;
    ((float4*)qmod)[idx] = v;
}

// ---------------------------------------------------------------------------
// z / q_mu / q_lv / logprob_q. QMU/QLV offsets are ODD -> scalar stores there.
// ---------------------------------------------------------------------------
__global__ __launch_bounds__(256)
void z_kernel(const float* __restrict__ qz, const float* __restrict__ eps,
              float* __restrict__ out) {
    int idx = blockIdx.x * 256 + threadIdx.x;   // B*CV*HW/4
    int e4 = idx << 2;
    int b = e4 >> 15;
    int r = e4 & 32767;
    int c = r >> 8;
    int pix = r & 255;
    float4 mu4 = *(const float4*)&qz[(((size_t)b * 256 + c) << 8) + pix];
    float4 lv4 = *(const float4*)&qz[(((size_t)b * 256 + 128 + c) << 8) + pix];
    float4 ep4 = ((const float4*)eps)[idx];
    float4 z4, lq4;
    float mu, lv, sd, lsd, e;
#define ZCOMP(F)                                     \
    mu = clamp10(mu4.F); lv = clamp10(lv4.F);        \
    sd = std_from_lv(lv); lsd = logstd_from_lv(lv);  \
    e = ep4.F;                                       \
    z4.F = mu + sd * e;                              \
    lq4.F = -0.5f * e * e - lsd - 0.5f * LOG2PI;     \
    mu4.F = mu; lv4.F = lv;
    ZCOMP(x) ZCOMP(y) ZCOMP(z) ZCOMP(w)
#undef ZCOMP
    ((float4*)(out + OFF_Z))[idx] = z4;
    ((float4*)(out + OFF_LPQ))[idx] = lq4;
    // misaligned regions: scalar
    float* qmu = out + OFF_QMU + e4;
    float* qlv = out + OFF_QLV + e4;
    qmu[0] = mu4.x; qmu[1] = mu4.y; qmu[2] = mu4.z; qmu[3] = mu4.w;
    qlv[0] = lv4.x; qlv[1] = lv4.y; qlv[2] = lv4.z; qlv[3] = lv4.w;
}

// ---------------------------------------------------------------------------
// logprob_p (layout [b,c,pix,k]) + fused KL(label) reduce (float4 over pix)
// ---------------------------------------------------------------------------
__global__ __launch_bounds__(256)
void pk_kernel(const float* __restrict__ p, const int* __restrict__ label,
               float* __restrict__ out) {
    int idx = blockIdx.x * 256 + threadIdx.x;   // B*CV*HW/4
    int e4 = idx << 2;
    int b = e4 >> 15;
    int r = e4 & 32767;
    int c = r >> 8;
    int pix = r & 255;
    int lbl = label[b];

    float4 z4 = ((const float4*)(out + OFF_Z))[idx];
    float zz[4] = {z4.x, z4.y, z4.z, z4.w};
    float qm[4], qs[4], lqs[4];
    const float* qmu = out + OFF_QMU + e4;
    const float* qlvp = out + OFF_QLV + e4;
#pragma unroll
    for (int j = 0; j < 4; j++) {
        qm[j] = qmu[j];
        float qlv = qlvp[j];
        qs[j] = std_from_lv(qlv);
        lqs[j] = logstd_from_lv(qlv);
    }

    float lp[4][4];
    float klv = 0.0f;
#pragma unroll
    for (int k = 0; k < K_; k++) {
        size_t base = (((size_t)b * (2 * K_ * CV_) + k * CV_ + c) << 8) + pix;
        float4 pm4 = *(const float4*)&p[base];
        float4 pl4 = *(const float4*)&p[base + ((size_t)(K_ * CV_) << 8)];
        float pmv[4] = {pm4.x, pm4.y, pm4.z, pm4.w};
        float plv[4] = {pl4.x, pl4.y, pl4.z, pl4.w};
#pragma unroll
        for (int j = 0; j < 4; j++) {
            float pm = clamp10(pmv[j]);
            float pv = clamp10(plv[j]);
            float ps = std_from_lv(pv);
            float lps = logstd_from_lv(pv);
            float inv_ps = 1.0f / ps;
            float d = (zz[j] - pm) * inv_ps;
            lp[j][k] = -0.5f * d * d - lps - 0.5f * LOG2PI;
            if (k == lbl) {
                float dd = qm[j] - pm;
                klv += lps - lqs[j] +
                       (qs[j] * qs[j] + dd * dd) * (0.5f * inv_ps * inv_ps) - 0.5f;
            }
        }
    }
    float4* lpp = (float4*)(out + OFF_LPP) + (size_t)e4;
#pragma unroll
    for (int j = 0; j < 4; j++)
        lpp[j] = make_float4(lp[j][0], lp[j][1], lp[j][2], lp[j][3]);

    __shared__ float red[256];
    red[threadIdx.x] = klv;
    __syncthreads();
    for (int s = 128; s > 0; s >>= 1) {
        if (threadIdx.x < s) red[threadIdx.x] += red[threadIdx.x + s];
        __syncthreads();
    }
    if (threadIdx.x == 0) atomicAdd(&g_kl_sum, (double)red[0]);
}

__global__ void finalize_kernel(float* __restrict__ out) {
    out[OFF_KLT] = (float)(g_kl_sum / (double)(B_ * CV_ * HW_) + g_js_mean);
}

// ---------------------------------------------------------------------------
// Launch
// ---------------------------------------------------------------------------
extern "C" void kernel_launch(void* const* d_in, const int* in_sizes, int n_in,
                              void* d_out, int out_size) {
    const float* p_params = (const float*)d_in[0];
    const float* q_params = (const float*)d_in[1];
    const int*   label    = (const int*)d_in[2];
    const float* eps      = (const float*)d_in[3];
    const float* u_gumbel = (const float*)d_in[4];
    const float* qy_conv_w = (const float*)d_in[5];
    const float* qy_conv_b = (const float*)d_in[6];
    const float* qy_lin_w  = (const float*)d_in[7];
    const float* qy_lin_b  = (const float*)d_in[8];
    const float* gamma_w   = (const float*)d_in[9];
    const float* gamma_b   = (const float*)d_in[10];
    const float* beta_w    = (const float*)d_in[11];
    const float* beta_b    = (const float*)d_in[12];
    const float* qz1_w     = (const float*)d_in[13];
    const float* qz1_b     = (const float*)d_in[14];
    const float* qz2_w     = (const float*)d_in[15];
    const float* qz2_b     = (const float*)d_in[16];
    const float* out_w     = (const float*)d_in[17];
    const float* out_b     = (const float*)d_in[18];
    float* out = (float*)d_out;

    float *h, *qmod, *t1, *qz, *logits, *gamma, *beta;
    uint32_t* wbuf;
    cudaGetSymbolAddress((void**)&h, g_h);
    cudaGetSymbolAddress((void**)&qmod, g_qmod);
    cudaGetSymbolAddress((void**)&t1, g_t1);
    cudaGetSymbolAddress((void**)&qz, g_qz);
    cudaGetSymbolAddress((void**)&logits, g_logits);
    cudaGetSymbolAddress((void**)&gamma, g_gamma);
    cudaGetSymbolAddress((void**)&beta, g_beta);
    cudaGetSymbolAddress((void**)&wbuf, g_wbuf);

    cudaFuncSetAttribute(conv_mma_kernel<CIN_, CV_, true>,
                         cudaFuncAttributeMaxDynamicSharedMemorySize, CONV_SMEM);
    cudaFuncSetAttribute(conv_mma_kernel<CIN_, 2 * CV_, true>,
                         cudaFuncAttributeMaxDynamicSharedMemorySize, CONV_SMEM);
    cudaFuncSetAttribute(conv_mma_kernel<2 * CV_, 2 * CV_, false>,
                         cudaFuncAttributeMaxDynamicSharedMemorySize, CONV_SMEM);
    cudaFuncSetAttribute(conv_mma_kernel<CV_, COUT_, false>,
                         cudaFuncAttributeMaxDynamicSharedMemorySize, CONV_SMEM);

    // 0) weight prep (fragment-ordered bf16 split)
    {
        int tq = 16 * 2 * 4608;
        wprep_kernel<<<(tq + 255) / 256, 256>>>(qy_conv_w, wbuf + WOFF_QY, CIN_, 2, tq);
        int t1n = 16 * 4 * 4608;
        wprep_kernel<<<(t1n + 255) / 256, 256>>>(qz1_w, wbuf + WOFF_QZ1, CIN_, 4, t1n);
        wprep_kernel<<<(t1n + 255) / 256, 256>>>(qz2_w, wbuf + WOFF_QZ2, 2 * CV_, 4, t1n);
        int to = 8 * 4 * 4608;
        wprep_kernel<<<(to + 255) / 256, 256>>>(out_w, wbuf + WOFF_OUT, CV_, 4, to);
    }

    // 1) h = relu(conv(q_params, qy_conv))
    conv_mma_kernel<CIN_, CV_, true><<<dim3(2, B_), 256, CONV_SMEM>>>(
        q_params, wbuf + WOFF_QY, qy_conv_b, h);
    // 2) qy_logits
    qy_lin_kernel<<<B_, 256>>>(h, qy_lin_w, qy_lin_b, logits);
    // 3) y / ce / js / gamma / beta
    small_kernel<<<1, 256>>>(logits, u_gumbel, label, gamma_w, gamma_b,
                             beta_w, beta_b, gamma, beta, out);
    // 4) q_mod
    qmod_kernel<<<(B_ * CIN_ * HW_) / 1024, 256>>>(q_params, gamma, beta, qmod);
    // 5) t1 = relu(conv(q_mod, qz1))
    conv_mma_kernel<CIN_, 2 * CV_, true><<<dim3(4, B_), 256, CONV_SMEM>>>(
        qmod, wbuf + WOFF_QZ1, qz1_b, t1);
    // 6) qz_params = conv(t1, qz2)
    conv_mma_kernel<2 * CV_, 2 * CV_, false><<<dim3(4, B_), 256, CONV_SMEM>>>(
        t1, wbuf + WOFF_QZ2, qz2_b, qz);
    // 7) z / q_mu / q_lv / logprob_q
    z_kernel<<<(B_ * CV_ * HW_) / 1024, 256>>>(qz, eps, out);
    // 8) out = conv(z, out_w)
    conv_mma_kernel<CV_, COUT_, false><<<dim3(4, B_), 256, CONV_SMEM>>>(
        out + OFF_Z, wbuf + WOFF_OUT, out_b, out + OFF_OUT);
    // 9) logprob_p + kl
    pk_kernel<<<(B_ * CV_ * HW_) / 1024, 256>>>(p_params, label, out);
    // 10) kl_total
    finalize_kernel<<<1, 1>>>(out);
}

// round 6
// speedup vs baseline: 7.4103x; 1.4659x over previous
#include <cuda_runtime.h>
#include <cuda_bf16.h>
#include <cuda_fp16.h>
#include <math.h>
#include <stdint.h>

// ---------------------------------------------------------------------------
// Problem constants
// ---------------------------------------------------------------------------
#define B_    256
#define K_    4
#define CIN_  256
#define CV_   128
#define COUT_ 256
#define HW_   256      // 16*16
#define LOG2PI 1.8378770664093453f

// Output layout (concatenated flat float32)
#define OFF_OUT 0
#define OFF_Z   16777216
#define OFF_LPP 25165824
#define OFF_LPQ 58720256
#define OFF_KLT 67108864
#define OFF_QMU 67108865   // ODD -> never access as float4!
#define OFF_QLV 75497473   // ODD -> never access as float4!
#define OFF_Y   83886081
#define OFF_CE  83887105

// ---------------------------------------------------------------------------
// Scratch (device-global; no runtime allocation). 16B-aligned for vector ops.
// ---------------------------------------------------------------------------
__device__ __align__(16) float  g_h[B_ * CV_ * HW_];
__device__ __align__(16) float  g_t1[B_ * 2 * CV_ * HW_];
__device__ __align__(16) float  g_qz[B_ * 2 * CV_ * HW_];
__device__ __align__(16) float  g_logits[B_ * K_];
__device__ __align__(16) float  g_gamma[B_ * CIN_];
__device__ __align__(16) float  g_beta[B_ * CIN_];
__device__ double g_kl_sum;
__device__ double g_js_mean;

// Fragment-ordered fp16 weights for the 4 convs. Per (chunk,ctile): 4608 words.
#define WOFF_QY  0          // 16*2*4608 = 147456
#define WOFF_QZ1 147456     // 16*4*4608 = 294912
#define WOFF_QZ2 442368     // 294912
#define WOFF_OUT 737280     // 8*4*4608 = 147456
#define WBUF_TOTAL 884736
__device__ __align__(16) uint32_t g_wbuf[WBUF_TOTAL];

// ---------------------------------------------------------------------------
// Helpers
// ---------------------------------------------------------------------------
__device__ __forceinline__ float clamp10(float v) {
    return fminf(fmaxf(v, -10.0f), 10.0f);
}
__device__ __forceinline__ float std_from_lv(float lv) {
    return (lv < 0.0f) ? expf(0.5f * lv) : (1.0f + lv);
}
__device__ __forceinline__ float logstd_from_lv(float lv) {
    return (lv < 0.0f) ? 0.5f * lv : log1pf(lv);
}
__device__ __forceinline__ uint32_t smem_u32(const void* p) {
    return (uint32_t)__cvta_generic_to_shared(p);
}
__device__ __forceinline__ uint32_t pack_h2(__half a, __half b) {
    return (uint32_t)__half_as_ushort(a) | ((uint32_t)__half_as_ushort(b) << 16);
}
__device__ __forceinline__ void ldsm4(uint32_t r[4], uint32_t addr) {
    asm volatile("ldmatrix.sync.aligned.m8n8.x4.shared.b16 {%0,%1,%2,%3}, [%4];"
                 : "=r"(r[0]), "=r"(r[1]), "=r"(r[2]), "=r"(r[3]) : "r"(addr));
}
__device__ __forceinline__ void mma16816(float c[4], const uint32_t a[4], uint32_t b0, uint32_t b1) {
    asm volatile(
        "mma.sync.aligned.m16n8k16.row.col.f32.f16.f16.f32 "
        "{%0,%1,%2,%3}, {%4,%5,%6,%7}, {%8,%9}, {%0,%1,%2,%3};"
        : "+f"(c[0]), "+f"(c[1]), "+f"(c[2]), "+f"(c[3])
        : "r"(a[0]), "r"(a[1]), "r"(a[2]), "r"(a[3]), "r"(b0), "r"(b1));
}

// ---------------------------------------------------------------------------
// Weight prep: fp32 w[co][ci][9] -> fragment-ordered fp16 words.
// slot s in [0,4608): s = ((t*8+nt)*32 + lane)*2 + reg
// word at blk*4608 + (t*8+nt)*64 + lane*2 + reg
// ---------------------------------------------------------------------------
__global__ void wprep_kernel(const float* __restrict__ w, uint32_t* __restrict__ dst,
                             int CIN, int CTILES, int total) {
    int idx = blockIdx.x * 256 + threadIdx.x;
    if (idx >= total) return;
    int s = idx % 4608;
    int blk = idx / 4608;             // chunk*CTILES + ctile
    int chunk = blk / CTILES;
    int ctile = blk % CTILES;
    int reg = s & 1;
    int lane = (s >> 1) & 31;
    int nt = (s >> 6) & 7;
    int t = s >> 9;
    int i = lane & 3, g = lane >> 2;
    int ci = chunk * 16 + 2 * i + 8 * reg;
    int co = ctile * 64 + nt * 8 + g;
    float f0 = w[(co * CIN + ci) * 9 + t];
    float f1 = w[(co * CIN + ci + 1) * 9 + t];
    uint32_t base = (uint32_t)blk * 4608u + (uint32_t)(t * 8 + nt) * 64u + lane * 2 + reg;
    dst[base] = pack_h2(__float2half_rn(f0), __float2half_rn(f1));
}

// ---------------------------------------------------------------------------
// Implicit-GEMM 3x3 conv via mma.sync, fp16 A hi/lo split x fp16 B.
// Block: 256 threads (8 warps). Tile: 1 image x 64 couts x 256 pixels.
// grid = (COUT/64, B). Dynamic smem: s_a (257*80 B) + s_b (4608 words).
// ---------------------------------------------------------------------------
#define CONV_SMEM (257 * 80 + 4608 * 4)   // 38992

template <int CIN, int COUT, bool RELU, bool AFFINE>
__global__ __launch_bounds__(256, 2)
void conv_mma_kernel(const float* __restrict__ in, const uint32_t* __restrict__ wbuf,
                     const float* __restrict__ bias, float* __restrict__ out,
                     const float* __restrict__ gamma, const float* __restrict__ beta) {
    extern __shared__ char smem[];
    char* s_a = smem;                                   // 257 rows * 80 B
    uint32_t* s_b = (uint32_t*)(smem + 257 * 80);       // 4608 words
    constexpr int CHUNKS = CIN / 16;
    constexpr int CTILES = COUT / 64;

    const int tid = threadIdx.x;
    const int lane = tid & 31;
    const int warp = tid >> 5;
    const int ctile = blockIdx.x;
    const int b = blockIdx.y;
    const int cout0 = ctile * 64;

    const uint32_t sa_base = smem_u32(s_a);

    // zero OOB row (row 256): 20 words
    if (tid < 20) ((uint32_t*)(s_a + 256 * 80))[tid] = 0;

    float acc[2][8][4];
#pragma unroll
    for (int mt = 0; mt < 2; mt++)
#pragma unroll
        for (int nt = 0; nt < 8; nt++)
#pragma unroll
            for (int j = 0; j < 4; j++) acc[mt][nt][j] = 0.0f;

    const int rowsel = lane & 15;   // x coordinate within the 16-pixel row
    const int khalf = lane >> 4;    // k half select (bytes +0 / +16)

    for (int ch = 0; ch < CHUNKS; ch++) {
        __syncthreads();
        // ---- load A tile: 16 channels x 256 pixels, fp16 hi/lo split ----
        const float* inp = in + (((size_t)b * CIN + ch * 16) << 8);
#pragma unroll
        for (int ci = 0; ci < 16; ci += 2) {
            float v0 = inp[(ci << 8) + tid];
            float v1 = inp[((ci + 1) << 8) + tid];
            if (AFFINE) {
                int c0 = b * CIN + ch * 16 + ci;
                v0 = gamma[c0] * v0 + beta[c0];
                v1 = gamma[c0 + 1] * v1 + beta[c0 + 1];
            }
            __half h0 = __float2half_rn(v0);
            __half h1 = __float2half_rn(v1);
            __half l0 = __float2half_rn(v0 - __half2float(h0));
            __half l1 = __float2half_rn(v1 - __half2float(h1));
            *(uint32_t*)(s_a + tid * 80 + ci * 2) = pack_h2(h0, h1);
            *(uint32_t*)(s_a + tid * 80 + 32 + ci * 2) = pack_h2(l0, l1);
        }
        // ---- load B tile: 1152 uint4 (fragment-linear) ----
        {
            const uint4* src = (const uint4*)(wbuf + ((size_t)(ch * CTILES + ctile)) * 4608u);
            uint4* dstb = (uint4*)s_b;
#pragma unroll
            for (int i = tid; i < 1152; i += 256) dstb[i] = src[i];
        }
        __syncthreads();

        // ---- compute ----
#pragma unroll
        for (int dy = 0; dy < 3; dy++) {
#pragma unroll
            for (int dx = 0; dx < 3; dx++) {
                const int t = dy * 3 + dx;
                // hoist B fragments for this tap (shared across mt)
                uint2 bw[8];
#pragma unroll
                for (int nt = 0; nt < 8; nt++)
                    bw[nt] = *(const uint2*)(s_b + (t * 8 + nt) * 64 + lane * 2);
                const int sx = rowsel + dx - 1;
                const bool colok = (unsigned)sx < 16u;
#pragma unroll
                for (int mt = 0; mt < 2; mt++) {
                    const int y = warp * 2 + mt;
                    const int sy = y + dy - 1;
                    const bool ok = colok && ((unsigned)sy < 16u);
                    const int spix = ok ? (sy * 16 + sx) : 256;
                    const uint32_t addr = sa_base + (uint32_t)spix * 80u + (uint32_t)khalf * 16u;
                    uint32_t ah[4], al[4];
                    ldsm4(ah, addr);
                    ldsm4(al, addr + 32u);
#pragma unroll
                    for (int nt = 0; nt < 8; nt++) {
                        mma16816(acc[mt][nt], ah, bw[nt].x, bw[nt].y);
                        mma16816(acc[mt][nt], al, bw[nt].x, bw[nt].y);
                    }
                }
            }
        }
    }

    // ---- epilogue: D[m=pixel][n=cout] -> out[b][co][pix], bias (+relu) ----
    const int g = lane >> 2;
    const int i2 = (lane & 3) * 2;
#pragma unroll
    for (int nt = 0; nt < 8; nt++) {
        const int co = cout0 + nt * 8 + i2;
        const float bz0 = bias[co];
        const float bz1 = bias[co + 1];
        float* o = out + (((size_t)b * COUT + co) << 8);
#pragma unroll
        for (int mt = 0; mt < 2; mt++) {
            const int pixa = warp * 32 + mt * 16 + g;
            float v0 = acc[mt][nt][0] + bz0;
            float v1 = acc[mt][nt][1] + bz1;
            float v2 = acc[mt][nt][2] + bz0;
            float v3 = acc[mt][nt][3] + bz1;
            if (RELU) {
                v0 = fmaxf(v0, 0.0f); v1 = fmaxf(v1, 0.0f);
                v2 = fmaxf(v2, 0.0f); v3 = fmaxf(v3, 0.0f);
            }
            o[pixa] = v0;
            o[256 + pixa] = v1;
            o[pixa + 8] = v2;
            o[256 + pixa + 8] = v3;
        }
    }
}

// ---------------------------------------------------------------------------
// qy_lin: logits[b,k] = sum_i h[b,i]*w[k,i] + bias[k]. One block per b.
// ---------------------------------------------------------------------------
__global__ __launch_bounds__(256)
void qy_lin_kernel(const float* __restrict__ h, const float* __restrict__ w,
                   const float* __restrict__ bias, float* __restrict__ logits) {
    const int b = blockIdx.x;
    const int tid = threadIdx.x;
    const int N = CV_ * HW_;     // 32768
    const int N4 = N / 4;
    float acc[K_] = {0, 0, 0, 0};
    const float4* hb = (const float4*)(h + (size_t)b * N);
    for (int i = tid; i < N4; i += 256) {
        float4 hv = hb[i];
#pragma unroll
        for (int k = 0; k < K_; k++) {
            float4 wv = ((const float4*)(w + (size_t)k * N))[i];
            acc[k] += hv.x * wv.x + hv.y * wv.y + hv.z * wv.z + hv.w * wv.w;
        }
    }
    __shared__ float red[256];
#pragma unroll
    for (int k = 0; k < K_; k++) {
        red[tid] = acc[k];
        __syncthreads();
        for (int s = 128; s > 0; s >>= 1) {
            if (tid < s) red[tid] += red[tid + s];
            __syncthreads();
        }
        if (tid == 0) logits[b * K_ + k] = red[0] + bias[k];
        __syncthreads();
    }
}

// ---------------------------------------------------------------------------
// Per-batch small work: gumbel softmax y, cross_entropy, js (scalars only).
// ---------------------------------------------------------------------------
__global__ __launch_bounds__(256)
void small_kernel(const float* __restrict__ logits, const float* __restrict__ u,
                  const int* __restrict__ label, float* __restrict__ out) {
    const int b = threadIdx.x;
    float l[K_], y[K_];
#pragma unroll
    for (int k = 0; k < K_; k++) l[k] = logits[b * K_ + k];

    float s[K_];
    float mx = -1e30f;
#pragma unroll
    for (int k = 0; k < K_; k++) {
        float uu = u[b * K_ + k];
        float g = -logf(-logf(uu));
        s[k] = l[k] + g;
        mx = fmaxf(mx, s[k]);
    }
    float sum = 0.0f;
#pragma unroll
    for (int k = 0; k < K_; k++) { y[k] = expf(s[k] - mx); sum += y[k]; }
    float inv = 1.0f / sum;
#pragma unroll
    for (int k = 0; k < K_; k++) {
        y[k] *= inv;
        out[OFF_Y + b * K_ + k] = y[k];
    }

    float mx2 = fmaxf(fmaxf(l[0], l[1]), fmaxf(l[2], l[3]));
    float se = 0.0f;
#pragma unroll
    for (int k = 0; k < K_; k++) se += expf(l[k] - mx2);
    float lse = logf(se) + mx2;
    int lbl = label[b];
    float ce_b = lse - l[lbl];

    const float prior = 1.0f / K_;
    float t1 = 0.0f, t2 = 0.0f;
#pragma unroll
    for (int k = 0; k < K_; k++) {
        float m = 0.5f * (y[k] + prior);
        t1 += y[k] * logf(y[k] / (m + 1e-10f));
        t2 += prior * logf(prior / (m + 1e-10f));
    }
    float js_b = 0.5f * t1 + 0.5f * t2;

    __shared__ double r1[256], r2[256];
    r1[b] = (double)ce_b;
    r2[b] = (double)js_b;
    __syncthreads();
    for (int st = 128; st > 0; st >>= 1) {
        if (b < st) { r1[b] += r1[b + st]; r2[b] += r2[b + st]; }
        __syncthreads();
    }
    if (b == 0) {
        out[OFF_CE] = (float)(r1[0] / (double)B_);
        g_js_mean = r2[0] / (double)B_;
        g_kl_sum = 0.0;
    }
}

// ---------------------------------------------------------------------------
// gamma/beta: one block per b, one thread per channel.
// ---------------------------------------------------------------------------
__global__ __launch_bounds__(256)
void gb_kernel(const float* __restrict__ logits,
               const float* __restrict__ gamma_w, const float* __restrict__ gamma_b,
               const float* __restrict__ beta_w, const float* __restrict__ beta_b,
               float* __restrict__ gamma, float* __restrict__ beta) {
    const int b = blockIdx.x;
    const int c = threadIdx.x;
    float l0 = logits[b * K_ + 0], l1 = logits[b * K_ + 1];
    float l2 = logits[b * K_ + 2], l3 = logits[b * K_ + 3];
    float4 gw = ((const float4*)gamma_w)[c];
    float4 bw = ((const float4*)beta_w)[c];
    gamma[b * CIN_ + c] = gw.x * l0 + gw.y * l1 + gw.z * l2 + gw.w * l3 + gamma_b[c];
    beta[b * CIN_ + c]  = bw.x * l0 + bw.y * l1 + bw.z * l2 + bw.w * l3 + beta_b[c];
}

// ---------------------------------------------------------------------------
// z / q_mu / q_lv / logprob_q. QMU/QLV offsets are ODD -> scalar stores there.
// ---------------------------------------------------------------------------
__global__ __launch_bounds__(256)
void z_kernel(const float* __restrict__ qz, const float* __restrict__ eps,
              float* __restrict__ out) {
    int idx = blockIdx.x * 256 + threadIdx.x;   // B*CV*HW/4
    int e4 = idx << 2;
    int b = e4 >> 15;
    int r = e4 & 32767;
    int c = r >> 8;
    int pix = r & 255;
    float4 mu4 = *(const float4*)&qz[(((size_t)b * 256 + c) << 8) + pix];
    float4 lv4 = *(const float4*)&qz[(((size_t)b * 256 + 128 + c) << 8) + pix];
    float4 ep4 = ((const float4*)eps)[idx];
    float4 z4, lq4;
    float mu, lv, sd, lsd, e;
#define ZCOMP(F)                                     \
    mu = clamp10(mu4.F); lv = clamp10(lv4.F);        \
    sd = std_from_lv(lv); lsd = logstd_from_lv(lv);  \
    e = ep4.F;                                       \
    z4.F = mu + sd * e;                              \
    lq4.F = -0.5f * e * e - lsd - 0.5f * LOG2PI;     \
    mu4.F = mu; lv4.F = lv;
    ZCOMP(x) ZCOMP(y) ZCOMP(z) ZCOMP(w)
#undef ZCOMP
    ((float4*)(out + OFF_Z))[idx] = z4;
    ((float4*)(out + OFF_LPQ))[idx] = lq4;
    // misaligned regions: scalar
    float* qmu = out + OFF_QMU + e4;
    float* qlv = out + OFF_QLV + e4;
    qmu[0] = mu4.x; qmu[1] = mu4.y; qmu[2] = mu4.z; qmu[3] = mu4.w;
    qlv[0] = lv4.x; qlv[1] = lv4.y; qlv[2] = lv4.z; qlv[3] = lv4.w;
}

// ---------------------------------------------------------------------------
// logprob_p (layout [b,c,pix,k]) + fused KL(label) reduce (float4 over pix)
// ---------------------------------------------------------------------------
__global__ __launch_bounds__(256)
void pk_kernel(const float* __restrict__ p, const int* __restrict__ label,
               float* __restrict__ out) {
    int idx = blockIdx.x * 256 + threadIdx.x;   // B*CV*HW/4
    int e4 = idx << 2;
    int b = e4 >> 15;
    int r = e4 & 32767;
    int c = r >> 8;
    int pix = r & 255;
    int lbl = label[b];

    float4 z4 = ((const float4*)(out + OFF_Z))[idx];
    float zz[4] = {z4.x, z4.y, z4.z, z4.w};
    float qm[4], qs[4], lqs[4];
    const float* qmu = out + OFF_QMU + e4;
    const float* qlvp = out + OFF_QLV + e4;
#pragma unroll
    for (int j = 0; j < 4; j++) {
        qm[j] = qmu[j];
        float qlv = qlvp[j];
        qs[j] = std_from_lv(qlv);
        lqs[j] = logstd_from_lv(qlv);
    }

    float lp[4][4];
    float klv = 0.0f;
#pragma unroll
    for (int k = 0; k < K_; k++) {
        size_t base = (((size_t)b * (2 * K_ * CV_) + k * CV_ + c) << 8) + pix;
        float4 pm4 = *(const float4*)&p[base];
        float4 pl4 = *(const float4*)&p[base + ((size_t)(K_ * CV_) << 8)];
        float pmv[4] = {pm4.x, pm4.y, pm4.z, pm4.w};
        float plv[4] = {pl4.x, pl4.y, pl4.z, pl4.w};
#pragma unroll
        for (int j = 0; j < 4; j++) {
            float pm = clamp10(pmv[j]);
            float pv = clamp10(plv[j]);
            float ps = std_from_lv(pv);
            float lps = logstd_from_lv(pv);
            float inv_ps = 1.0f / ps;
            float d = (zz[j] - pm) * inv_ps;
            lp[j][k] = -0.5f * d * d - lps - 0.5f * LOG2PI;
            if (k == lbl) {
                float dd = qm[j] - pm;
                klv += lps - lqs[j] +
                       (qs[j] * qs[j] + dd * dd) * (0.5f * inv_ps * inv_ps) - 0.5f;
            }
        }
    }
    float4* lpp = (float4*)(out + OFF_LPP) + (size_t)e4;
#pragma unroll
    for (int j = 0; j < 4; j++)
        lpp[j] = make_float4(lp[j][0], lp[j][1], lp[j][2], lp[j][3]);

    __shared__ float red[256];
    red[threadIdx.x] = klv;
    __syncthreads();
    for (int s = 128; s > 0; s >>= 1) {
        if (threadIdx.x < s) red[threadIdx.x] += red[threadIdx.x + s];
        __syncthreads();
    }
    if (threadIdx.x == 0) atomicAdd(&g_kl_sum, (double)red[0]);
}

__global__ void finalize_kernel(float* __restrict__ out) {
    out[OFF_KLT] = (float)(g_kl_sum / (double)(B_ * CV_ * HW_) + g_js_mean);
}

// ---------------------------------------------------------------------------
// Launch
// ---------------------------------------------------------------------------
extern "C" void kernel_launch(void* const* d_in, const int* in_sizes, int n_in,
                              void* d_out, int out_size) {
    const float* p_params = (const float*)d_in[0];
    const float* q_params = (const float*)d_in[1];
    const int*   label    = (const int*)d_in[2];
    const float* eps      = (const float*)d_in[3];
    const float* u_gumbel = (const float*)d_in[4];
    const float* qy_conv_w = (const float*)d_in[5];
    const float* qy_conv_b = (const float*)d_in[6];
    const float* qy_lin_w  = (const float*)d_in[7];
    const float* qy_lin_b  = (const float*)d_in[8];
    const float* gamma_w   = (const float*)d_in[9];
    const float* gamma_b   = (const float*)d_in[10];
    const float* beta_w    = (const float*)d_in[11];
    const float* beta_b    = (const float*)d_in[12];
    const float* qz1_w     = (const float*)d_in[13];
    const float* qz1_b     = (const float*)d_in[14];
    const float* qz2_w     = (const float*)d_in[15];
    const float* qz2_b     = (const float*)d_in[16];
    const float* out_w     = (const float*)d_in[17];
    const float* out_b     = (const float*)d_in[18];
    float* out = (float*)d_out;

    float *h, *t1, *qz, *logits, *gamma, *beta;
    uint32_t* wbuf;
    cudaGetSymbolAddress((void**)&h, g_h);
    cudaGetSymbolAddress((void**)&t1, g_t1);
    cudaGetSymbolAddress((void**)&qz, g_qz);
    cudaGetSymbolAddress((void**)&logits, g_logits);
    cudaGetSymbolAddress((void**)&gamma, g_gamma);
    cudaGetSymbolAddress((void**)&beta, g_beta);
    cudaGetSymbolAddress((void**)&wbuf, g_wbuf);

    cudaFuncSetAttribute(conv_mma_kernel<CIN_, CV_, true, false>,
                         cudaFuncAttributeMaxDynamicSharedMemorySize, CONV_SMEM);
    cudaFuncSetAttribute(conv_mma_kernel<CIN_, 2 * CV_, true, true>,
                         cudaFuncAttributeMaxDynamicSharedMemorySize, CONV_SMEM);
    cudaFuncSetAttribute(conv_mma_kernel<2 * CV_, 2 * CV_, false, false>,
                         cudaFuncAttributeMaxDynamicSharedMemorySize, CONV_SMEM);
    cudaFuncSetAttribute(conv_mma_kernel<CV_, COUT_, false, false>,
                         cudaFuncAttributeMaxDynamicSharedMemorySize, CONV_SMEM);

    // 0) weight prep (fragment-ordered fp16)
    {
        int tq = 16 * 2 * 4608;
        wprep_kernel<<<(tq + 255) / 256, 256>>>(qy_conv_w, wbuf + WOFF_QY, CIN_, 2, tq);
        int t1n = 16 * 4 * 4608;
        wprep_kernel<<<(t1n + 255) / 256, 256>>>(qz1_w, wbuf + WOFF_QZ1, CIN_, 4, t1n);
        wprep_kernel<<<(t1n + 255) / 256, 256>>>(qz2_w, wbuf + WOFF_QZ2, 2 * CV_, 4, t1n);
        int to = 8 * 4 * 4608;
        wprep_kernel<<<(to + 255) / 256, 256>>>(out_w, wbuf + WOFF_OUT, CV_, 4, to);
    }

    // 1) h = relu(conv(q_params, qy_conv))
    conv_mma_kernel<CIN_, CV_, true, false><<<dim3(2, B_), 256, CONV_SMEM>>>(
        q_params, wbuf + WOFF_QY, qy_conv_b, h, nullptr, nullptr);
    // 2) qy_logits
    qy_lin_kernel<<<B_, 256>>>(h, qy_lin_w, qy_lin_b, logits);
    // 3) y / ce / js  +  gamma/beta
    small_kernel<<<1, 256>>>(logits, u_gumbel, label, out);
    gb_kernel<<<B_, 256>>>(logits, gamma_w, gamma_b, beta_w, beta_b, gamma, beta);
    // 4+5) t1 = relu(conv(gamma*q+beta, qz1))  (affine fused into A load)
    conv_mma_kernel<CIN_, 2 * CV_, true, true><<<dim3(4, B_), 256, CONV_SMEM>>>(
        q_params, wbuf + WOFF_QZ1, qz1_b, t1, gamma, beta);
    // 6) qz_params = conv(t1, qz2)
    conv_mma_kernel<2 * CV_, 2 * CV_, false, false><<<dim3(4, B_), 256, CONV_SMEM>>>(
        t1, wbuf + WOFF_QZ2, qz2_b, qz, nullptr, nullptr);
    // 7) z / q_mu / q_lv / logprob_q
    z_kernel<<<(B_ * CV_ * HW_) / 1024, 256>>>(qz, eps, out);
    // 8) out = conv(z, out_w)
    conv_mma_kernel<CV_, COUT_, false, false><<<dim3(4, B_), 256, CONV_SMEM>>>(
        out + OFF_Z, wbuf + WOFF_OUT, out_b, out + OFF_OUT, nullptr, nullptr);
    // 9) logprob_p + kl
    pk_kernel<<<(B_ * CV_ * HW_) / 1024, 256>>>(p_params, label, out);
    // 10) kl_total
    finalize_kernel<<<1, 1>>>(out);
}